// round 3
// baseline (speedup 1.0000x reference)
#include <cuda_runtime.h>
#include <math.h>

// Problem dims
#define BSZ 2
#define SEQ 512
#define HID 1024
#define NHD 16
#define HDD 64
#define NL  4
#define FFD 4096
#define NCL 14
#define TOK (BSZ*SEQ)          // 1024
#define SHs (SEQ*HID)          // 524288   per-batch stride in q/k/v/x
#define HSC (SEQ*SEQ)          // 262144   per-head stride in score buffers
#define ZSC (NHD*SEQ*SEQ)      // 4194304  per-batch stride in score buffers

// ---------------- scratch (device globals: no cudaMalloc allowed) -------------
__device__ float g_x[TOK*HID];
__device__ float g_q[TOK*HID];
__device__ float g_k[TOK*HID];
__device__ float g_v[TOK*HID];
__device__ float g_rel[SEQ*HID];
__device__ float g_pk[SEQ*HID];
__device__ float g_pq[SEQ*HID];
__device__ float g_sc[BSZ*NHD*SEQ*SEQ];
__device__ float g_c2p[BSZ*NHD*SEQ*SEQ];
__device__ float g_p2c[BSZ*NHD*SEQ*SEQ];
__device__ float g_ctx[TOK*HID];
__device__ float g_ff[TOK*FFD];
__device__ int   g_idxm[SEQ*SEQ];
__device__ float g_nll[TOK];

// ---------------- block reduction helper (blockDim.x multiple of 32) ----------
__device__ __forceinline__ float blk_sum(float v, float* red) {
    #pragma unroll
    for (int o = 16; o; o >>= 1) v += __shfl_down_sync(0xffffffffu, v, o);
    int w = threadIdx.x >> 5, lane = threadIdx.x & 31;
    int nw = blockDim.x >> 5;
    __syncthreads();                 // guard red reuse
    if (lane == 0) red[w] = v;
    __syncthreads();
    if (threadIdx.x == 0) { float s = 0.f; for (int i = 0; i < nw; i++) s += red[i]; red[0] = s; }
    __syncthreads();
    return red[0];
}

// ---------------- generic fp32 GEMM: C = act(A @ op(B) + bias) ----------------
// Tile 128(M) x 64(N), BK=16, 256 threads, 8x4 per-thread microtile.
// TB=true -> B given as [N,K] row-major (computes A @ B^T).
// z-dim batching: z -> (zb, zh) with per-axis pointer strides (attention heads).
template<int ACT, bool TB>
__global__ __launch_bounds__(256)
void sgemm_k(const float* __restrict__ A, const float* __restrict__ Bm,
             float* __restrict__ C, const float* __restrict__ bias,
             int K, int lda, int ldb, int ldc,
             long aB, long aH, long bB, long bH, long cB, long cH, int nh)
{
    int z = blockIdx.z;
    int zb = z / nh, zh = z - zb * nh;
    A  += zb * aB + zh * aH;
    Bm += zb * bB + zh * bH;
    C  += zb * cB + zh * cH;

    __shared__ float As[16][132];    // [k][m], padded
    __shared__ float Bs[16][68];     // [k][n], padded

    const int tid  = threadIdx.x;
    const int tx   = tid & 15;
    const int ty   = tid >> 4;
    const int m0   = blockIdx.y << 7;
    const int n0   = blockIdx.x << 6;
    const int lrow = tid >> 2;           // 0..63
    const int lcol = (tid & 3) << 2;     // 0,4,8,12

    float acc[8][4];
    #pragma unroll
    for (int i = 0; i < 8; i++)
        #pragma unroll
        for (int j = 0; j < 4; j++) acc[i][j] = 0.f;

    for (int k0 = 0; k0 < K; k0 += 16) {
        float4 a0 = *(const float4*)(A + (long)(m0 + lrow)      * lda + k0 + lcol);
        float4 a1 = *(const float4*)(A + (long)(m0 + lrow + 64) * lda + k0 + lcol);
        As[lcol+0][lrow] = a0.x; As[lcol+1][lrow] = a0.y;
        As[lcol+2][lrow] = a0.z; As[lcol+3][lrow] = a0.w;
        As[lcol+0][lrow+64] = a1.x; As[lcol+1][lrow+64] = a1.y;
        As[lcol+2][lrow+64] = a1.z; As[lcol+3][lrow+64] = a1.w;
        if (TB) {
            float4 bv = *(const float4*)(Bm + (long)(n0 + lrow) * ldb + k0 + lcol);
            Bs[lcol+0][lrow] = bv.x; Bs[lcol+1][lrow] = bv.y;
            Bs[lcol+2][lrow] = bv.z; Bs[lcol+3][lrow] = bv.w;
        } else {
            int br = tid >> 4, bc = (tid & 15) << 2;
            *(float4*)&Bs[br][bc] = *(const float4*)(Bm + (long)(k0 + br) * ldb + n0 + bc);
        }
        __syncthreads();
        #pragma unroll
        for (int kk = 0; kk < 16; kk++) {
            float4 af0 = *(const float4*)&As[kk][ty << 3];
            float4 af1 = *(const float4*)&As[kk][(ty << 3) + 4];
            float4 bf  = *(const float4*)&Bs[kk][tx << 2];
            float ar[8] = {af0.x, af0.y, af0.z, af0.w, af1.x, af1.y, af1.z, af1.w};
            float br[4] = {bf.x, bf.y, bf.z, bf.w};
            #pragma unroll
            for (int i = 0; i < 8; i++)
                #pragma unroll
                for (int j = 0; j < 4; j++)
                    acc[i][j] = fmaf(ar[i], br[j], acc[i][j]);
        }
        __syncthreads();
    }

    const int col = n0 + (tx << 2);
    #pragma unroll
    for (int i = 0; i < 8; i++) {
        int row = m0 + (ty << 3) + i;
        float vv[4];
        #pragma unroll
        for (int j = 0; j < 4; j++) {
            float v = acc[i][j];
            if (bias) v += bias[col + j];
            if (ACT == 1) v = 0.5f * v * (1.0f + erff(v * 0.70710678118654752f)); // exact gelu
            vv[j] = v;
        }
        *(float4*)(C + (long)row * ldc + col) = make_float4(vv[0], vv[1], vv[2], vv[3]);
    }
}

// ---------------- embedding: x = LN(word_emb[id]) * maskf ---------------------
__global__ void embed_ln_k(const float* __restrict__ emb,
                           const float* __restrict__ s, const float* __restrict__ b,
                           const int* __restrict__ ids, const int* __restrict__ am,
                           float* __restrict__ out)
{
    __shared__ float sh[HID];
    __shared__ float red[8];
    int tok = blockIdx.x;
    long ebase = (long)ids[tok] * HID;
    float m = (float)am[tok];
    float ls = 0.f;
    for (int i = threadIdx.x; i < HID; i += blockDim.x) { float v = emb[ebase + i]; sh[i] = v; ls += v; }
    __syncthreads();
    float mu = blk_sum(ls, red) * (1.0f / HID);
    float lv = 0.f;
    for (int i = threadIdx.x; i < HID; i += blockDim.x) { float d = sh[i] - mu; lv += d * d; }
    float var = blk_sum(lv, red) * (1.0f / HID);
    float r = rsqrtf(var + 1e-7f);
    long obase = (long)tok * HID;
    for (int i = threadIdx.x; i < HID; i += blockDim.x)
        out[obase + i] = ((sh[i] - mu) * r * s[i] + b[i]) * m;
}

// ---------------- residual + LN: out = LN((res?) + t) -------------------------
__global__ void add_ln_k(const float* res, const float* __restrict__ t,
                         const float* __restrict__ s, const float* __restrict__ b,
                         float* out)
{
    __shared__ float sh[HID];
    __shared__ float red[8];
    long base = (long)blockIdx.x * HID;
    float ls = 0.f;
    for (int i = threadIdx.x; i < HID; i += blockDim.x) {
        float v = t[base + i];
        if (res) v += res[base + i];
        sh[i] = v; ls += v;
    }
    __syncthreads();
    float mu = blk_sum(ls, red) * (1.0f / HID);
    float lv = 0.f;
    for (int i = threadIdx.x; i < HID; i += blockDim.x) { float d = sh[i] - mu; lv += d * d; }
    float var = blk_sum(lv, red) * (1.0f / HID);
    float r = rsqrtf(var + 1e-7f);
    for (int i = threadIdx.x; i < HID; i += blockDim.x)
        out[base + i] = (sh[i] - mu) * r * s[i] + b[i];
}

// ---------------- DeBERTa log-bucket relative index ---------------------------
// J[q,k] = clip(relb(q-k) + 256, 0, 511); also serves the p2c gather (antisymmetry).
__global__ void build_idx_k(int* __restrict__ idxm)
{
    int q = blockIdx.x;
    const int mid = 128;
    for (int k = threadIdx.x; k < SEQ; k += blockDim.x) {
        int rel = q - k;
        int a = (rel < mid && rel > -mid) ? (mid - 1) : (rel < 0 ? -rel : rel);
        int bucket;
        if (a <= mid) bucket = rel;
        else {
            float lp = ceilf(logf((float)a / (float)mid) / logf(511.0f / (float)mid) * (float)(mid - 1))
                       + (float)mid;
            float sgn = (rel > 0) ? 1.f : ((rel < 0) ? -1.f : 0.f);
            bucket = (int)(lp * sgn);
        }
        int J = bucket + 256;
        J = J < 0 ? 0 : (J > 511 ? 511 : J);
        idxm[q * SEQ + k] = J;
    }
}

// ------- combine + mask + softmax:  probs = softmax((qk + c2p[J] + p2c[J])/scale)
__global__ void attn_softmax_k(float* __restrict__ sc, const float* __restrict__ c2p,
                               const float* __restrict__ p2c, const int* __restrict__ idxm,
                               const int* __restrict__ am)
{
    __shared__ float red[4];
    int q = blockIdx.x, z = blockIdx.y;
    int b = z >> 4;                     // NHD = 16
    long ro = ((long)z * SEQ + q) * (long)SEQ;
    float* row = sc + ro;
    const float* cr = c2p + ro;
    const float* pb = p2c + (long)z * SEQ * 512;
    int mq = am[b * SEQ + q];
    const float scale = sqrtf(3.0f * (float)HDD);
    float vals[4]; int msk[4];
    float mx = -3.402823466e38f;
    #pragma unroll
    for (int t = 0; t < 4; t++) {
        int k = threadIdx.x + t * 128;
        int J = idxm[q * SEQ + k];
        float v = (row[k] + cr[J] + pb[(long)k * 512 + J]) / scale;
        int mk = mq & am[b * SEQ + k];
        vals[t] = v; msk[t] = mk;
        if (mk) mx = fmaxf(mx, v);
    }
    #pragma unroll
    for (int o = 16; o; o >>= 1) mx = fmaxf(mx, __shfl_down_sync(0xffffffffu, mx, o));
    if ((threadIdx.x & 31) == 0) red[threadIdx.x >> 5] = mx;
    __syncthreads();
    mx = fmaxf(fmaxf(red[0], red[1]), fmaxf(red[2], red[3]));
    float ls = 0.f;
    #pragma unroll
    for (int t = 0; t < 4; t++) {
        float e = msk[t] ? expf(vals[t] - mx) : 0.f;
        vals[t] = e; ls += e;
    }
    __syncthreads();
    #pragma unroll
    for (int o = 16; o; o >>= 1) ls += __shfl_down_sync(0xffffffffu, ls, o);
    if ((threadIdx.x & 31) == 0) red[threadIdx.x >> 5] = ls;
    __syncthreads();
    float sum = red[0] + red[1] + red[2] + red[3];
    float inv = sum > 0.f ? 1.0f / sum : 0.f;
    #pragma unroll
    for (int t = 0; t < 4; t++) row[threadIdx.x + t * 128] = vals[t] * inv;
}

// ---------------- decoder (N=14) + per-row masked NLL -------------------------
__global__ void decoder_k(const float* __restrict__ t, const float* __restrict__ Wd,
                          const float* __restrict__ bd, const int* __restrict__ labels,
                          const int* __restrict__ am, float* __restrict__ out,
                          int logit_limit, float* __restrict__ nll)
{
    __shared__ float sh[HID];
    __shared__ float wred[4][NCL];
    __shared__ float lg[NCL];
    int row = blockIdx.x;
    long base = (long)row * HID;
    for (int i = threadIdx.x; i < HID; i += 128) sh[i] = t[base + i];
    __syncthreads();
    float p[NCL];
    #pragma unroll
    for (int c = 0; c < NCL; c++) p[c] = 0.f;
    for (int i = threadIdx.x; i < HID; i += 128) {
        float tv = sh[i];
        const float* w = Wd + (long)i * NCL;
        #pragma unroll
        for (int c = 0; c < NCL; c++) p[c] = fmaf(tv, w[c], p[c]);
    }
    #pragma unroll
    for (int c = 0; c < NCL; c++)
        #pragma unroll
        for (int o = 16; o; o >>= 1) p[c] += __shfl_down_sync(0xffffffffu, p[c], o);
    if ((threadIdx.x & 31) == 0) {
        int w = threadIdx.x >> 5;
        #pragma unroll
        for (int c = 0; c < NCL; c++) wred[w][c] = p[c];
    }
    __syncthreads();
    if (threadIdx.x < NCL) {
        float v = wred[0][threadIdx.x] + wred[1][threadIdx.x]
                + wred[2][threadIdx.x] + wred[3][threadIdx.x] + bd[threadIdx.x];
        lg[threadIdx.x] = v;
        int oi = row * NCL + threadIdx.x;
        if (oi < logit_limit) out[oi] = v;
    }
    __syncthreads();
    if (threadIdx.x == 0) {
        float m = lg[0];
        #pragma unroll
        for (int c = 1; c < NCL; c++) m = fmaxf(m, lg[c]);
        float ssum = 0.f;
        #pragma unroll
        for (int c = 0; c < NCL; c++) ssum += expf(lg[c] - m);
        float lse = m + logf(ssum);
        float nl = lse - lg[labels[row]];
        nll[row] = nl * (float)am[row];
    }
}

__global__ void finalize_k(const float* __restrict__ nll, const int* __restrict__ am,
                           float* __restrict__ out, int loss_idx)
{
    __shared__ float red[8];
    float a = 0.f, bm = 0.f;
    for (int i = threadIdx.x; i < TOK; i += 256) { a += nll[i]; bm += (float)am[i]; }
    float sa = blk_sum(a, red);
    float sb = blk_sum(bm, red);
    if (threadIdx.x == 0 && loss_idx >= 0) out[loss_idx] = sa / fmaxf(sb, 1.0f);
}

// ------------------------------- host driver ----------------------------------
extern "C" void kernel_launch(void* const* d_in, const int* in_sizes, int n_in,
                              void* d_out, int out_size)
{
    (void)in_sizes; (void)n_in;
    const float* word_emb = (const float*)d_in[0];
    const float* emb_ln_s = (const float*)d_in[1];
    const float* emb_ln_b = (const float*)d_in[2];
    const float* rel_emb  = (const float*)d_in[3];
    const float* rel_ln_s = (const float*)d_in[4];
    const float* rel_ln_b = (const float*)d_in[5];
    const float* Wq = (const float*)d_in[6];
    const float* bq = (const float*)d_in[7];
    const float* Wk = (const float*)d_in[8];
    const float* bk = (const float*)d_in[9];
    const float* Wv = (const float*)d_in[10];
    const float* bv = (const float*)d_in[11];
    const float* Wo = (const float*)d_in[12];
    const float* bo = (const float*)d_in[13];
    const float* ln1_s = (const float*)d_in[14];
    const float* ln1_b = (const float*)d_in[15];
    const float* W1 = (const float*)d_in[16];
    const float* b1 = (const float*)d_in[17];
    const float* W2 = (const float*)d_in[18];
    const float* b2 = (const float*)d_in[19];
    const float* ln2_s = (const float*)d_in[20];
    const float* ln2_b = (const float*)d_in[21];
    const float* Wt = (const float*)d_in[22];
    const float* bt = (const float*)d_in[23];
    const float* tln_s = (const float*)d_in[24];
    const float* tln_b = (const float*)d_in[25];
    const float* Wd = (const float*)d_in[26];
    const float* bd = (const float*)d_in[27];
    const int* ids    = (const int*)d_in[28];
    const int* am     = (const int*)d_in[29];
    const int* labels = (const int*)d_in[30];
    float* out = (float*)d_out;

    float *x, *q, *k, *v, *rel, *pk, *pq, *sc, *c2p, *p2c, *ctx, *ff, *nll;
    int* idxm;
    cudaGetSymbolAddress((void**)&x,   g_x);
    cudaGetSymbolAddress((void**)&q,   g_q);
    cudaGetSymbolAddress((void**)&k,   g_k);
    cudaGetSymbolAddress((void**)&v,   g_v);
    cudaGetSymbolAddress((void**)&rel, g_rel);
    cudaGetSymbolAddress((void**)&pk,  g_pk);
    cudaGetSymbolAddress((void**)&pq,  g_pq);
    cudaGetSymbolAddress((void**)&sc,  g_sc);
    cudaGetSymbolAddress((void**)&c2p, g_c2p);
    cudaGetSymbolAddress((void**)&p2c, g_p2c);
    cudaGetSymbolAddress((void**)&ctx, g_ctx);
    cudaGetSymbolAddress((void**)&ff,  g_ff);
    cudaGetSymbolAddress((void**)&nll, g_nll);
    cudaGetSymbolAddress((void**)&idxm, g_idxm);

    build_idx_k<<<SEQ, 128>>>(idxm);
    embed_ln_k<<<TOK, 256>>>(word_emb, emb_ln_s, emb_ln_b, ids, am, x);
    add_ln_k<<<SEQ, 256>>>(nullptr, rel_emb, rel_ln_s, rel_ln_b, rel);

    const dim3 gProj(HID / 64, TOK / 128, 1);     // (16, 8)
    const dim3 gPos(HID / 64, SEQ / 128, 1);      // (16, 4)
    const dim3 gAtt(SEQ / 64, SEQ / 128, BSZ * NHD);  // (8, 4, 32)
    const dim3 gCtx(1, SEQ / 128, BSZ * NHD);     // (1, 4, 32)
    const dim3 gFF1(FFD / 64, TOK / 128, 1);      // (64, 8)

    for (int l = 0; l < NL; l++) {
        const float* Wq_l = Wq + (long)l * HID * HID;
        const float* Wk_l = Wk + (long)l * HID * HID;
        const float* Wv_l = Wv + (long)l * HID * HID;
        const float* Wo_l = Wo + (long)l * HID * HID;
        const float* bq_l = bq + l * HID;
        const float* bk_l = bk + l * HID;
        const float* bv_l = bv + l * HID;
        const float* bo_l = bo + l * HID;
        const float* W1_l = W1 + (long)l * HID * FFD;
        const float* b1_l = b1 + l * FFD;
        const float* W2_l = W2 + (long)l * FFD * HID;
        const float* b2_l = b2 + l * HID;

        // Q/K/V projections
        sgemm_k<0, false><<<gProj, 256>>>(x, Wq_l, q, bq_l, HID, HID, HID, HID, 0,0,0,0,0,0, 1);
        sgemm_k<0, false><<<gProj, 256>>>(x, Wk_l, k, bk_l, HID, HID, HID, HID, 0,0,0,0,0,0, 1);
        sgemm_k<0, false><<<gProj, 256>>>(x, Wv_l, v, bv_l, HID, HID, HID, HID, 0,0,0,0,0,0, 1);
        // positional keys/queries (share_att_key): rel_ln @ Wk/Wq + bias
        sgemm_k<0, false><<<gPos, 256>>>(rel, Wk_l, pk, bk_l, HID, HID, HID, HID, 0,0,0,0,0,0, 1);
        sgemm_k<0, false><<<gPos, 256>>>(rel, Wq_l, pq, bq_l, HID, HID, HID, HID, 0,0,0,0,0,0, 1);
        // attention GEMMs (A @ B^T per (b,h)): qk, c2p, p2c
        sgemm_k<0, true><<<gAtt, 256>>>(q, k,  sc,  nullptr, HDD, HID, HID, SEQ,
                                        SHs, HDD, SHs, HDD, ZSC, HSC, NHD);
        sgemm_k<0, true><<<gAtt, 256>>>(q, pk, c2p, nullptr, HDD, HID, HID, 512,
                                        SHs, HDD, 0,   HDD, ZSC, HSC, NHD);
        sgemm_k<0, true><<<gAtt, 256>>>(k, pq, p2c, nullptr, HDD, HID, HID, 512,
                                        SHs, HDD, 0,   HDD, ZSC, HSC, NHD);
        // combine disentangled biases + mask + softmax (in-place -> probs)
        attn_softmax_k<<<dim3(SEQ, BSZ * NHD), 128>>>(sc, c2p, p2c, idxm, am);
        // ctx = probs @ V
        sgemm_k<0, false><<<gCtx, 256>>>(sc, v, ctx, nullptr, SEQ, SEQ, HID, HID,
                                         ZSC, HSC, SHs, HDD, SHs, HDD, NHD);
        // output proj + residual LN
        sgemm_k<0, false><<<gProj, 256>>>(ctx, Wo_l, ff, bo_l, HID, HID, HID, HID, 0,0,0,0,0,0, 1);
        add_ln_k<<<TOK, 256>>>(x, ff, ln1_s + l * HID, ln1_b + l * HID, x);
        // FFN
        sgemm_k<1, false><<<gFF1, 256>>>(x, W1_l, ff, b1_l, HID, HID, FFD, FFD, 0,0,0,0,0,0, 1);
        sgemm_k<0, false><<<gProj, 256>>>(ff, W2_l, ctx, b2_l, FFD, FFD, HID, HID, 0,0,0,0,0,0, 1);
        add_ln_k<<<TOK, 256>>>(x, ctx, ln2_s + l * HID, ln2_b + l * HID, x);
    }

    // transform head: LN(gelu(x @ Wt + bt))
    sgemm_k<1, false><<<gProj, 256>>>(x, Wt, ff, bt, HID, HID, HID, HID, 0,0,0,0,0,0, 1);
    add_ln_k<<<TOK, 256>>>(nullptr, ff, tln_s, tln_b, q);   // reuse q buffer as t

    int logits_n = TOK * NCL;                               // 14336
    int logit_limit = (out_size > 1) ? (out_size < logits_n ? out_size : logits_n) : 0;
    int loss_idx = (out_size == 1) ? 0 : (out_size > logits_n ? logits_n : -1);
    decoder_k<<<TOK, 128>>>(q, Wd, bd, labels, am, out, logit_limit, nll);
    finalize_k<<<1, 256>>>(nll, am, out, loss_idx);
}